// round 3
// baseline (speedup 1.0000x reference)
#include <cuda_runtime.h>
#include <cuda_bf16.h>
#include <cstdint>

#define B_    8
#define C_    256
#define N_    1024
#define NH    8
#define HD    32
#define R_    4
#define MTOT  776          // 256 q + 256 k + 256 v + 4 sq + 4 sk
#define SCALE 0.17677669529663689f   // 32^-0.5

// ---------------- scratch (static device globals; no runtime alloc) ----------------
__device__ float g_wall[MTOT * C_];          // stacked weights [776][256]
__device__ float g_ball[MTOT];
__device__ float g_proj[B_ * MTOT * N_];     // projections [B][776][1024]
__device__ float g_sq[B_ * N_];
__device__ float g_sk[B_ * N_];
__device__ float g_attnout[B_ * C_ * N_];    // attention output [B][256][1024]

// ---------------- kernel 0: assemble stacked weight matrix ----------------
__global__ void assemble_kernel(const float* __restrict__ Wq, const float* __restrict__ bq,
                                const float* __restrict__ Wk, const float* __restrict__ bk,
                                const float* __restrict__ Wv, const float* __restrict__ bv,
                                const float* __restrict__ Wsq, const float* __restrict__ bsq,
                                const float* __restrict__ Wsk, const float* __restrict__ bsk) {
    int o = blockIdx.x;
    int k = threadIdx.x;
    const float* src; const float* bs; int r;
    if (o < 256)      { src = Wq  + o * 256;        bs = bq;  r = o; }
    else if (o < 512) { src = Wk  + (o-256) * 256;  bs = bk;  r = o - 256; }
    else if (o < 768) { src = Wv  + (o-512) * 256;  bs = bv;  r = o - 512; }
    else if (o < 772) { src = Wsq + (o-768) * 256;  bs = bsq; r = o - 768; }
    else              { src = Wsk + (o-772) * 256;  bs = bsk; r = o - 772; }
    g_wall[o * 256 + k] = src[k];
    if (k == 0) g_ball[o] = bs[r];
}

// ---------------- generic per-batch GEMM: Y[b][o][n] = sum_c W[o][c] X[b][c][n] + bias[o] ----------------
#define BM 64
#define BN 64
#define BK 32
__global__ __launch_bounds__(256) void gemm_kernel(
    const float* __restrict__ W, const float* __restrict__ bias,
    const float* __restrict__ X, float* __restrict__ Y,
    int M, long xStride, long yStride)
{
    int b  = blockIdx.z;
    int m0 = blockIdx.y * BM;
    int n0 = blockIdx.x * BN;
    const float* Xb = X + (long)b * xStride;
    float*       Yb = Y + (long)b * yStride;

    __shared__ float sW[BK][BM];   // sW[k][m]
    __shared__ float sX[BK][BN];   // sX[k][n]

    int tid = threadIdx.x;
    int tx = tid & 15;   // -> n
    int ty = tid >> 4;   // -> m
    float acc[4][4] = {};

    for (int k0 = 0; k0 < C_; k0 += BK) {
        // W tile (BM x BK), transposed into sW[k][m]
        #pragma unroll
        for (int i = tid; i < BM * BK; i += 256) {
            int m = i / BK, k = i % BK;
            int gm = m0 + m;
            float v = 0.f;
            if (gm < M) v = W[gm * C_ + k0 + k];
            sW[k][m] = v;
        }
        // X tile (BK x BN)
        #pragma unroll
        for (int i = tid; i < BK * BN; i += 256) {
            int k = i / BN, n = i % BN;
            sX[k][n] = Xb[(k0 + k) * N_ + n0 + n];
        }
        __syncthreads();
        #pragma unroll
        for (int k = 0; k < BK; k++) {
            float a[4], bb[4];
            #pragma unroll
            for (int i = 0; i < 4; i++) a[i] = sW[k][ty * 4 + i];
            #pragma unroll
            for (int j = 0; j < 4; j++) bb[j] = sX[k][tx * 4 + j];
            #pragma unroll
            for (int i = 0; i < 4; i++)
                #pragma unroll
                for (int j = 0; j < 4; j++) acc[i][j] += a[i] * bb[j];
        }
        __syncthreads();
    }
    #pragma unroll
    for (int i = 0; i < 4; i++) {
        int gm = m0 + ty * 4 + i;
        if (gm >= M) continue;
        float bv = bias[gm];
        #pragma unroll
        for (int j = 0; j < 4; j++)
            Yb[(long)gm * N_ + n0 + tx * 4 + j] = acc[i][j] + bv;
    }
}

// ---------------- gates: 4-way softmax per pixel, keep channel 0 ----------------
__global__ void gates_kernel(const float* __restrict__ gq, const float* __restrict__ gk) {
    int idx = blockIdx.x * blockDim.x + threadIdx.x;   // b*1024 + n
    if (idx >= B_ * N_) return;
    int b = idx >> 10, n = idx & 1023;
    const float* pr = g_proj + (long)b * MTOT * N_;

    float lq[R_], lk[R_];
    #pragma unroll
    for (int r = 0; r < R_; r++) {
        lq[r] = pr[(768 + r) * N_ + n] + gq[(b * R_ + r) * N_ + n];
        lk[r] = pr[(772 + r) * N_ + n] + gk[(b * R_ + r) * N_ + n];
    }
    float mq = fmaxf(fmaxf(lq[0], lq[1]), fmaxf(lq[2], lq[3]));
    float sq = 0.f;
    #pragma unroll
    for (int r = 0; r < R_; r++) sq += __expf(lq[r] - mq);
    g_sq[idx] = __expf(lq[0] - mq) / sq;

    float mk = fmaxf(fmaxf(lk[0], lk[1]), fmaxf(lk[2], lk[3]));
    float sk = 0.f;
    #pragma unroll
    for (int r = 0; r < R_; r++) sk += __expf(lk[r] - mk);
    g_sk[idx] = __expf(lk[0] - mk) / sk;
}

// ---------------- scale q rows by sq*SCALE, k rows by sk (in place) ----------------
__global__ void scale_qk_kernel() {
    int idx = blockIdx.x * blockDim.x + threadIdx.x;   // over B*512*1024
    if (idx >= B_ * 512 * N_) return;
    int n = idx & 1023;
    int c = (idx >> 10) & 511;
    int b = idx >> 19;
    float* pr = g_proj + (long)b * MTOT * N_;
    if (c < 256) pr[c * N_ + n]        *= g_sq[b * N_ + n] * SCALE;
    else         pr[c * N_ + n]        *= g_sk[b * N_ + n];
}

// ---------------- flash attention per (b, h, 64-query tile) ----------------
#define NQ 64
#define NKT 64
__global__ __launch_bounds__(256) void attn_kernel() {
    int b  = blockIdx.z;
    int h  = blockIdx.y;
    int n0 = blockIdx.x * NQ;
    const float* qb = g_proj + ((long)b * MTOT + h * HD) * N_;
    const float* kb = g_proj + ((long)b * MTOT + 256 + h * HD) * N_;
    const float* vb = g_proj + ((long)b * MTOT + 512 + h * HD) * N_;

    __shared__ float sQ[HD][NQ];
    __shared__ float sK[HD][NKT];
    __shared__ float sV[HD][NKT];
    __shared__ float sP[NQ][NKT + 1];   // padded: odd stride kills bank conflicts
    __shared__ float sC[NQ];
    __shared__ float sL[NQ];

    int tid = threadIdx.x;
    // score-thread mapping (16x16, 4x4 microtile)
    int tq = tid >> 4, tm = tid & 15;
    // O-thread mapping (2 d-rows x 4 q per thread)
    int oq = tid & 15, od = tid >> 4;

    for (int i = tid; i < HD * NQ; i += 256) {
        int d = i / NQ, q = i % NQ;
        sQ[d][q] = qb[d * N_ + n0 + q];
    }

    float run_m[4], run_l[4];
    #pragma unroll
    for (int i = 0; i < 4; i++) { run_m[i] = -1e30f; run_l[i] = 0.f; }
    float acc[2][4] = {};

    __syncthreads();

    for (int m0 = 0; m0 < N_; m0 += NKT) {
        for (int i = tid; i < HD * NKT; i += 256) {
            int d = i / NKT, m = i % NKT;
            sK[d][m] = kb[d * N_ + m0 + m];
            sV[d][m] = vb[d * N_ + m0 + m];
        }
        __syncthreads();

        // scores 4x4 per thread
        float s[4][4] = {};
        #pragma unroll
        for (int d = 0; d < HD; d++) {
            float a[4], bb[4];
            #pragma unroll
            for (int i = 0; i < 4; i++) a[i] = sQ[d][tq * 4 + i];
            #pragma unroll
            for (int j = 0; j < 4; j++) bb[j] = sK[d][tm * 4 + j];
            #pragma unroll
            for (int i = 0; i < 4; i++)
                #pragma unroll
                for (int j = 0; j < 4; j++) s[i][j] += a[i] * bb[j];
        }

        // online softmax per row (rows replicated across the 16 tm threads)
        #pragma unroll
        for (int i = 0; i < 4; i++) {
            float mx = s[i][0];
            #pragma unroll
            for (int j = 1; j < 4; j++) mx = fmaxf(mx, s[i][j]);
            #pragma unroll
            for (int off = 1; off < 16; off <<= 1)
                mx = fmaxf(mx, __shfl_xor_sync(0xffffffffu, mx, off, 16));
            float newm = fmaxf(run_m[i], mx);
            float corr = __expf(run_m[i] - newm);
            float rs = 0.f;
            float p[4];
            #pragma unroll
            for (int j = 0; j < 4; j++) { p[j] = __expf(s[i][j] - newm); rs += p[j]; }
            #pragma unroll
            for (int off = 1; off < 16; off <<= 1)
                rs += __shfl_xor_sync(0xffffffffu, rs, off, 16);
            run_l[i] = run_l[i] * corr + rs;
            run_m[i] = newm;
            #pragma unroll
            for (int j = 0; j < 4; j++) sP[tq * 4 + i][tm * 4 + j] = p[j];
            if (tm == 0) sC[tq * 4 + i] = corr;
        }
        __syncthreads();

        // O update: acc[dd][qq] = acc*corr + P @ V^T
        #pragma unroll
        for (int qq = 0; qq < 4; qq++) {
            float c = sC[oq * 4 + qq];
            acc[0][qq] *= c;
            acc[1][qq] *= c;
        }
        #pragma unroll
        for (int m = 0; m < NKT; m++) {
            float v0 = sV[od * 2][m], v1 = sV[od * 2 + 1][m];
            #pragma unroll
            for (int qq = 0; qq < 4; qq++) {
                float p = sP[oq * 4 + qq][m];
                acc[0][qq] += v0 * p;
                acc[1][qq] += v1 * p;
            }
        }
        __syncthreads();
    }

    if (tm == 0) {
        #pragma unroll
        for (int i = 0; i < 4; i++) sL[tq * 4 + i] = run_l[i];
    }
    __syncthreads();

    float* ob = g_attnout + ((long)b * C_ + h * HD) * N_;
    #pragma unroll
    for (int qq = 0; qq < 4; qq++) {
        int q = oq * 4 + qq;
        float inv = 1.f / sL[q];
        ob[(od * 2) * N_ + n0 + q]     = acc[0][qq] * inv;
        ob[(od * 2 + 1) * N_ + n0 + q] = acc[1][qq] * inv;
    }
}

// ---------------- blend: v-rows of proj <- sq*attn_out + (1-sq)*v (in place) ----------------
__global__ void combine_kernel() {
    int idx = blockIdx.x * blockDim.x + threadIdx.x;   // over B*256*1024
    if (idx >= B_ * C_ * N_) return;
    int n = idx & 1023;
    int c = (idx >> 10) & 255;
    int b = idx >> 18;
    float sq = g_sq[b * N_ + n];
    float* vp = g_proj + ((long)b * MTOT + 512 + c) * N_ + n;
    float o  = g_attnout[((long)b * C_ + c) * N_ + n];
    *vp = sq * o + (1.f - sq) * (*vp);
}

// ---------------- launch ----------------
extern "C" void kernel_launch(void* const* d_in, const int* in_sizes, int n_in,
                              void* d_out, int out_size) {
    const float* x   = (const float*)d_in[0];
    const float* gq  = (const float*)d_in[1];
    const float* gk  = (const float*)d_in[2];
    const float* Wsq = (const float*)d_in[3];
    const float* bsq = (const float*)d_in[4];
    const float* Wsk = (const float*)d_in[5];
    const float* bsk = (const float*)d_in[6];
    const float* Wq  = (const float*)d_in[7];
    const float* bq  = (const float*)d_in[8];
    const float* Wk  = (const float*)d_in[9];
    const float* bk  = (const float*)d_in[10];
    const float* Wv  = (const float*)d_in[11];
    const float* bv  = (const float*)d_in[12];
    const float* Wp  = (const float*)d_in[13];
    const float* bp  = (const float*)d_in[14];
    float* out = (float*)d_out;

    void *wall_p = nullptr, *ball_p = nullptr, *proj_p = nullptr;
    cudaGetSymbolAddress(&wall_p, g_wall);
    cudaGetSymbolAddress(&ball_p, g_ball);
    cudaGetSymbolAddress(&proj_p, g_proj);

    // 1. assemble stacked weights
    assemble_kernel<<<MTOT, 256>>>(Wq, bq, Wk, bk, Wv, bv, Wsq, bsq, Wsk, bsk);

    // 2. fused projection GEMM: proj = Wall @ x  (per batch)
    {
        dim3 g(N_ / BN, (MTOT + BM - 1) / BM, B_);
        gemm_kernel<<<g, 256>>>((const float*)wall_p, (const float*)ball_p,
                                x, (float*)proj_p,
                                MTOT, (long)C_ * N_, (long)MTOT * N_);
    }

    // 3. gumbel-softmax gates
    gates_kernel<<<(B_ * N_ + 255) / 256, 256>>>(gq, gk);

    // 4. scale q,k rows by gates (+SCALE folded into q)
    scale_qk_kernel<<<(B_ * 512 * N_ + 255) / 256, 256>>>();

    // 5. attention
    {
        dim3 g(N_ / NQ, NH, B_);
        attn_kernel<<<g, 256>>>();
    }

    // 6. blend gate output with v shortcut (in place into proj v-rows)
    combine_kernel<<<(B_ * C_ * N_ + 255) / 256, 256>>>();

    // 7. final projection GEMM: out = Wp @ gated
    {
        dim3 g(N_ / BN, C_ / BM, B_);
        gemm_kernel<<<g, 256>>>(Wp, bp,
                                (const float*)proj_p + 512 * N_, out,
                                C_, (long)MTOT * N_, (long)C_ * N_);
    }
}

// round 4
// speedup vs baseline: 2.6899x; 2.6899x over previous
#include <cuda_runtime.h>
#include <cuda_bf16.h>
#include <cstdint>

#define B_    8
#define C_    256
#define N_    1024
#define NH    8
#define HD    32
#define R_    4
#define MTOT  776
#define SCALE 0.17677669529663689f
#define LOG2E 1.4426950408889634f

// ---------------- scratch ----------------
__device__ float g_proj[B_ * MTOT * N_];
__device__ float g_sq[B_ * N_];
__device__ float g_sk[B_ * N_];
__device__ float g_ball[MTOT];
__device__ __nv_bfloat16 g_whi[MTOT * C_], g_wlo[MTOT * C_];
__device__ __nv_bfloat16 g_wphi[C_ * C_], g_wplo[C_ * C_];
__device__ __nv_bfloat16 g_xhi[B_ * C_ * N_], g_xlo[B_ * C_ * N_];
__device__ __nv_bfloat16 g_qT[B_ * NH * N_ * HD];   // [b][h][n][d], gate*SCALE*LOG2E applied
__device__ __nv_bfloat16 g_kB[B_ * NH * HD * N_];   // [b][h][d][n], gate applied
__device__ __nv_bfloat16 g_vB[B_ * NH * HD * N_];   // [b][h][d][n]
__device__ __nv_bfloat16 g_ghi[B_ * C_ * N_], g_glo[B_ * C_ * N_];

// ---------------- ptx helpers ----------------
__device__ __forceinline__ void cp16(void* d, const void* s) {
    uint32_t ds = (uint32_t)__cvta_generic_to_shared(d);
    asm volatile("cp.async.cg.shared.global [%0], [%1], 16;" :: "r"(ds), "l"(s));
}
__device__ __forceinline__ void cp_commit() { asm volatile("cp.async.commit_group;"); }

__device__ __forceinline__ void ldsm_x4(uint32_t (&r)[4], const void* p) {
    uint32_t a = (uint32_t)__cvta_generic_to_shared(p);
    asm volatile("ldmatrix.sync.aligned.m8n8.x4.shared.b16 {%0,%1,%2,%3},[%4];"
                 : "=r"(r[0]), "=r"(r[1]), "=r"(r[2]), "=r"(r[3]) : "r"(a));
}
__device__ __forceinline__ void ldsm_x2(uint32_t (&r)[2], const void* p) {
    uint32_t a = (uint32_t)__cvta_generic_to_shared(p);
    asm volatile("ldmatrix.sync.aligned.m8n8.x2.shared.b16 {%0,%1},[%2];"
                 : "=r"(r[0]), "=r"(r[1]) : "r"(a));
}
__device__ __forceinline__ void ldsm_x2t(uint32_t (&r)[2], const void* p) {
    uint32_t a = (uint32_t)__cvta_generic_to_shared(p);
    asm volatile("ldmatrix.sync.aligned.m8n8.x2.trans.shared.b16 {%0,%1},[%2];"
                 : "=r"(r[0]), "=r"(r[1]) : "r"(a));
}
__device__ __forceinline__ void mma16816(float (&d)[4], const uint32_t (&a)[4], const uint32_t (&b)[2]) {
    asm volatile(
        "mma.sync.aligned.m16n8k16.row.col.f32.bf16.bf16.f32 "
        "{%0,%1,%2,%3},{%4,%5,%6,%7},{%8,%9},{%0,%1,%2,%3};"
        : "+f"(d[0]), "+f"(d[1]), "+f"(d[2]), "+f"(d[3])
        : "r"(a[0]), "r"(a[1]), "r"(a[2]), "r"(a[3]), "r"(b[0]), "r"(b[1]));
}
__device__ __forceinline__ uint32_t packbf(float lo, float hi) {
    __nv_bfloat162 t = __floats2bfloat162_rn(lo, hi);   // .x = lo (low 16 bits)
    return *reinterpret_cast<uint32_t*>(&t);
}
__device__ __forceinline__ float ex2(float x) {
    float y; asm("ex2.approx.ftz.f32 %0,%1;" : "=f"(y) : "f"(x)); return y;
}
__device__ __forceinline__ void split_bf(float x, __nv_bfloat16& hi, __nv_bfloat16& lo) {
    hi = __float2bfloat16_rn(x);
    lo = __float2bfloat16_rn(x - __bfloat162float(hi));
}

// ---------------- assemble + split weights ----------------
__global__ void assemble_split_kernel(
    const float* __restrict__ Wq, const float* __restrict__ bq,
    const float* __restrict__ Wk, const float* __restrict__ bk,
    const float* __restrict__ Wv, const float* __restrict__ bv,
    const float* __restrict__ Wsq, const float* __restrict__ bsq,
    const float* __restrict__ Wsk, const float* __restrict__ bsk,
    const float* __restrict__ Wp)
{
    int o = blockIdx.x;
    int k = threadIdx.x;
    if (o < MTOT) {
        const float* src; const float* bs; int r;
        if (o < 256)      { src = Wq  + o * 256;       bs = bq;  r = o; }
        else if (o < 512) { src = Wk  + (o-256) * 256; bs = bk;  r = o - 256; }
        else if (o < 768) { src = Wv  + (o-512) * 256; bs = bv;  r = o - 512; }
        else if (o < 772) { src = Wsq + (o-768) * 256; bs = bsq; r = o - 768; }
        else              { src = Wsk + (o-772) * 256; bs = bsk; r = o - 772; }
        __nv_bfloat16 hi, lo; split_bf(src[k], hi, lo);
        g_whi[o * 256 + k] = hi; g_wlo[o * 256 + k] = lo;
        if (k == 0) g_ball[o] = bs[r];
    } else {
        int r = o - MTOT;
        __nv_bfloat16 hi, lo; split_bf(Wp[r * 256 + k], hi, lo);
        g_wphi[r * 256 + k] = hi; g_wplo[r * 256 + k] = lo;
    }
}

// ---------------- split x into bf16 hi/lo ----------------
__global__ void xsplit_kernel(const float* __restrict__ x) {
    int i = blockIdx.x * 256 + threadIdx.x;
    __nv_bfloat16 hi, lo; split_bf(x[i], hi, lo);
    g_xhi[i] = hi; g_xlo[i] = lo;
}

// ---------------- bf16x3 GEMM: Y[b][m][n] = W @ X + bias ----------------
// block 128x128, 256 threads (8 warps: 2M x 4N), K=256, BK=16, cp.async 2-stage.
__global__ __launch_bounds__(256) void gemm3x_kernel(
    const __nv_bfloat16* __restrict__ Whi, const __nv_bfloat16* __restrict__ Wlo,
    const float* __restrict__ bias,
    const __nv_bfloat16* __restrict__ Xhi, const __nv_bfloat16* __restrict__ Xlo,
    float* __restrict__ Y, int M, long xStride, long yStride)
{
    int b  = blockIdx.z;
    int m0 = blockIdx.y * 128;
    int n0 = blockIdx.x * 128;
    const __nv_bfloat16* XhiB = Xhi + (long)b * xStride;
    const __nv_bfloat16* XloB = Xlo + (long)b * xStride;

    __shared__ __align__(16) __nv_bfloat16 sA[2][2][128 * 16];   // [stage][var][m][k], 32B rows
    __shared__ __align__(16) __nv_bfloat16 sB[2][2][16 * 136];   // [stage][var][k][n], 272B rows (pad 8)

    int tid  = threadIdx.x;
    int warp = tid >> 5, lane = tid & 31;
    int wm = warp >> 2, wn = warp & 3;
    int g = lane >> 2, t = lane & 3;

    float acc[4][4][4];
    #pragma unroll
    for (int mi = 0; mi < 4; mi++)
        #pragma unroll
        for (int ni = 0; ni < 4; ni++)
            #pragma unroll
            for (int r = 0; r < 4; r++) acc[mi][ni][r] = 0.f;

    auto loadStage = [&](int step, int s) {
        int k0 = step * 16;
        {   // A: 128 rows x 32B = 256 chunks per var; 1 chunk each per thread
            int row = tid >> 1, half = tid & 1;
            int gm = m0 + row;
            __nv_bfloat16* dhi = &sA[s][0][row * 16 + half * 8];
            __nv_bfloat16* dlo = &sA[s][1][row * 16 + half * 8];
            if (gm < M) {
                cp16(dhi, Whi + gm * 256 + k0 + half * 8);
                cp16(dlo, Wlo + gm * 256 + k0 + half * 8);
            } else {
                *reinterpret_cast<uint4*>(dhi) = make_uint4(0,0,0,0);
                *reinterpret_cast<uint4*>(dlo) = make_uint4(0,0,0,0);
            }
        }
        {   // B: 16 rows x 256B = 256 chunks per var
            int row = tid >> 4, seg = tid & 15;
            cp16(&sB[s][0][row * 136 + seg * 8], XhiB + (long)(k0 + row) * N_ + n0 + seg * 8);
            cp16(&sB[s][1][row * 136 + seg * 8], XloB + (long)(k0 + row) * N_ + n0 + seg * 8);
        }
        cp_commit();
    };

    loadStage(0, 0);
    for (int step = 0; step < 16; step++) {
        int s = step & 1;
        if (step < 15) {
            loadStage(step + 1, s ^ 1);
            asm volatile("cp.async.wait_group 1;");
        } else {
            asm volatile("cp.async.wait_group 0;");
        }
        __syncthreads();

        uint32_t afr[2][4][4];
        #pragma unroll
        for (int v = 0; v < 2; v++)
            #pragma unroll
            for (int mi = 0; mi < 4; mi++) {
                const __nv_bfloat16* p = &sA[s][v][(wm * 64 + mi * 16 + (lane & 15)) * 16] + ((lane >> 4) & 1) * 8;
                ldsm_x4(afr[v][mi], p);
            }
        uint32_t bfr[2][4][2];
        #pragma unroll
        for (int v = 0; v < 2; v++)
            #pragma unroll
            for (int ni = 0; ni < 4; ni++) {
                const __nv_bfloat16* p = &sB[s][v][(lane & 15) * 136 + wn * 32 + ni * 8];
                ldsm_x2t(bfr[v][ni], p);
            }
        #pragma unroll
        for (int mi = 0; mi < 4; mi++)
            #pragma unroll
            for (int ni = 0; ni < 4; ni++) {
                mma16816(acc[mi][ni], afr[0][mi], bfr[0][ni]);
                mma16816(acc[mi][ni], afr[0][mi], bfr[1][ni]);
                mma16816(acc[mi][ni], afr[1][mi], bfr[0][ni]);
            }
        __syncthreads();
    }

    float* Yb = Y + (long)b * yStride;
    #pragma unroll
    for (int mi = 0; mi < 4; mi++) {
        int r0 = m0 + wm * 64 + mi * 16 + g;
        int r1 = r0 + 8;
        #pragma unroll
        for (int ni = 0; ni < 4; ni++) {
            int col = n0 + wn * 32 + ni * 8 + 2 * t;
            if (r0 < M) {
                float bv = bias[r0];
                Yb[(long)r0 * N_ + col]     = acc[mi][ni][0] + bv;
                Yb[(long)r0 * N_ + col + 1] = acc[mi][ni][1] + bv;
            }
            if (r1 < M) {
                float bv = bias[r1];
                Yb[(long)r1 * N_ + col]     = acc[mi][ni][2] + bv;
                Yb[(long)r1 * N_ + col + 1] = acc[mi][ni][3] + bv;
            }
        }
    }
}

// ---------------- gates: 4-way softmax per pixel ----------------
__global__ void gates_kernel(const float* __restrict__ gq, const float* __restrict__ gk) {
    int idx = blockIdx.x * blockDim.x + threadIdx.x;
    if (idx >= B_ * N_) return;
    int b = idx >> 10, n = idx & 1023;
    const float* pr = g_proj + (long)b * MTOT * N_;
    float lq[R_], lk[R_];
    #pragma unroll
    for (int r = 0; r < R_; r++) {
        lq[r] = pr[(768 + r) * N_ + n] + gq[(b * R_ + r) * N_ + n];
        lk[r] = pr[(772 + r) * N_ + n] + gk[(b * R_ + r) * N_ + n];
    }
    float mq = fmaxf(fmaxf(lq[0], lq[1]), fmaxf(lq[2], lq[3]));
    float sq = 0.f;
    #pragma unroll
    for (int r = 0; r < R_; r++) sq += __expf(lq[r] - mq);
    g_sq[idx] = __expf(lq[0] - mq) / sq;
    float mk = fmaxf(fmaxf(lk[0], lk[1]), fmaxf(lk[2], lk[3]));
    float sk = 0.f;
    #pragma unroll
    for (int r = 0; r < R_; r++) sk += __expf(lk[r] - mk);
    g_sk[idx] = __expf(lk[0] - mk) / sk;
}

// ---------------- convert: q->qT (gated, scaled, log2e), k->kB (gated), v->vB ----------------
__global__ __launch_bounds__(256) void convert_kernel() {
    int bh = blockIdx.x;
    int b = bh >> 3, h = bh & 7;
    int tid = threadIdx.x;
    const float* qrow = g_proj + ((long)b * MTOT + h * HD) * N_;
    const float* krow = g_proj + ((long)b * MTOT + 256 + h * HD) * N_;
    const float* vrow = g_proj + ((long)b * MTOT + 512 + h * HD) * N_;
    __nv_bfloat16* qT = g_qT + (long)bh * N_ * HD;
    __nv_bfloat16* kB = g_kB + (long)bh * HD * N_;
    __nv_bfloat16* vB = g_vB + (long)bh * HD * N_;
    const float QMUL = SCALE * LOG2E;

    __shared__ __nv_bfloat16 tsm[32][264];
    for (int c = 0; c < 4; c++) {
        int n0 = c * 256;
        for (int i = tid; i < 32 * 256; i += 256) {
            int d = i >> 8, n = i & 255;
            tsm[d][n] = __float2bfloat16_rn(qrow[d * N_ + n0 + n] * g_sq[b * N_ + n0 + n] * QMUL);
        }
        __syncthreads();
        for (int i = tid; i < 256 * 32; i += 256) {
            int n = i >> 5, d = i & 31;
            qT[(long)(n0 + n) * HD + d] = tsm[d][n];
        }
        __syncthreads();
    }
    for (int i = tid; i < HD * N_; i += 256) {
        int d = i >> 10, n = i & 1023;
        kB[d * N_ + n] = __float2bfloat16_rn(krow[d * N_ + n] * g_sk[b * N_ + n]);
        vB[d * N_ + n] = __float2bfloat16_rn(vrow[d * N_ + n]);
    }
}

// ---------------- flash attention (mma.sync bf16) + fused gate blend ----------------
// block: 128 threads (4 warps x 16 queries = 64 queries), all 1024 keys in 64-key tiles.
__global__ __launch_bounds__(128) void attn_kernel() {
    int b = blockIdx.z, h = blockIdx.y;
    int n0 = blockIdx.x * 64;
    int bh = b * NH + h;
    const __nv_bfloat16* qTp = g_qT + ((long)bh * N_ + n0) * HD;
    const __nv_bfloat16* kBp = g_kB + (long)bh * HD * N_;
    const __nv_bfloat16* vBp = g_vB + (long)bh * HD * N_;

    __shared__ __align__(16) __nv_bfloat16 qsm[64 * 32];       // [q][d], 64B rows
    __shared__ __align__(16) __nv_bfloat16 ksm[32 * 72];       // [d][key], 144B rows
    __shared__ __align__(16) __nv_bfloat16 vsm[32 * 72];
    __shared__ float osm[32][65];

    int tid = threadIdx.x;
    int w = tid >> 5, lane = tid & 31;
    int g = lane >> 2, t = lane & 3;

    // load Q tile (64 x 32 bf16 = 4KB = 256 x 16B)
    for (int c = tid; c < 256; c += 128) {
        int row = c >> 2, seg = c & 3;
        reinterpret_cast<uint4*>(qsm + row * 32)[seg] =
            reinterpret_cast<const uint4*>(qTp + (long)row * HD)[seg];
    }
    __syncthreads();

    uint32_t aq[2][4];
    #pragma unroll
    for (int ku = 0; ku < 2; ku++) {
        const __nv_bfloat16* p = qsm + (w * 16 + (lane & 15)) * 32 + ku * 16 + ((lane >> 4) & 1) * 8;
        ldsm_x4(aq[ku], p);
    }

    float oacc[4][4];
    #pragma unroll
    for (int nd = 0; nd < 4; nd++)
        #pragma unroll
        for (int r = 0; r < 4; r++) oacc[nd][r] = 0.f;
    float run_m0 = -1e30f, run_m1 = -1e30f, run_l0 = 0.f, run_l1 = 0.f;

    for (int m0 = 0; m0 < N_; m0 += 64) {
        __syncthreads();
        // load K,V tiles: 32 rows x 128B = 256 x 16B chunks each
        for (int c = tid; c < 256; c += 128) {
            int row = c >> 3, seg = c & 7;
            reinterpret_cast<uint4*>(ksm + row * 72)[seg] =
                reinterpret_cast<const uint4*>(kBp + (long)row * N_ + m0)[seg];
            reinterpret_cast<uint4*>(vsm + row * 72)[seg] =
                reinterpret_cast<const uint4*>(vBp + (long)row * N_ + m0)[seg];
        }
        __syncthreads();

        // S = Q^T K : 8 n-frags of 16x8
        float sS[8][4];
        #pragma unroll
        for (int ni = 0; ni < 8; ni++) {
            #pragma unroll
            for (int r = 0; r < 4; r++) sS[ni][r] = 0.f;
            #pragma unroll
            for (int ku = 0; ku < 2; ku++) {
                uint32_t bk[2];
                ldsm_x2t(bk, ksm + (ku * 16 + (lane & 15)) * 72 + ni * 8);
                mma16816(sS[ni], aq[ku], bk);
            }
        }

        // online softmax (log2 domain; q pre-scaled by LOG2E)
        float mx0 = -1e30f, mx1 = -1e30f;
        #pragma unroll
        for (int ni = 0; ni < 8; ni++) {
            mx0 = fmaxf(mx0, fmaxf(sS[ni][0], sS[ni][1]));
            mx1 = fmaxf(mx1, fmaxf(sS[ni][2], sS[ni][3]));
        }
        #pragma unroll
        for (int off = 1; off < 4; off <<= 1) {
            mx0 = fmaxf(mx0, __shfl_xor_sync(0xffffffffu, mx0, off));
            mx1 = fmaxf(mx1, __shfl_xor_sync(0xffffffffu, mx1, off));
        }
        float nm0 = fmaxf(run_m0, mx0), nm1 = fmaxf(run_m1, mx1);
        float cr0 = ex2(run_m0 - nm0), cr1 = ex2(run_m1 - nm1);
        float ts0 = 0.f, ts1 = 0.f;
        #pragma unroll
        for (int ni = 0; ni < 8; ni++) {
            sS[ni][0] = ex2(sS[ni][0] - nm0); ts0 += sS[ni][0];
            sS[ni][1] = ex2(sS[ni][1] - nm0); ts0 += sS[ni][1];
            sS[ni][2] = ex2(sS[ni][2] - nm1); ts1 += sS[ni][2];
            sS[ni][3] = ex2(sS[ni][3] - nm1); ts1 += sS[ni][3];
        }
        #pragma unroll
        for (int off = 1; off < 4; off <<= 1) {
            ts0 += __shfl_xor_sync(0xffffffffu, ts0, off);
            ts1 += __shfl_xor_sync(0xffffffffu, ts1, off);
        }
        run_l0 = run_l0 * cr0 + ts0; run_m0 = nm0;
        run_l1 = run_l1 * cr1 + ts1; run_m1 = nm1;
        #pragma unroll
        for (int nd = 0; nd < 4; nd++) {
            oacc[nd][0] *= cr0; oacc[nd][1] *= cr0;
            oacc[nd][2] *= cr1; oacc[nd][3] *= cr1;
        }

        // O += P V^T
        #pragma unroll
        for (int u = 0; u < 4; u++) {
            uint32_t ap[4];
            ap[0] = packbf(sS[2*u][0],   sS[2*u][1]);
            ap[1] = packbf(sS[2*u][2],   sS[2*u][3]);
            ap[2] = packbf(sS[2*u+1][0], sS[2*u+1][1]);
            ap[3] = packbf(sS[2*u+1][2], sS[2*u+1][3]);
            #pragma unroll
            for (int nd = 0; nd < 4; nd++) {
                uint32_t bv[2];
                ldsm_x2(bv, vsm + (nd * 8 + (lane & 7)) * 72 + u * 16 + ((lane >> 3) & 1) * 8);
                mma16816(oacc[nd], ap, bv);
            }
        }
    }

    // epilogue: normalize, stage transposed, blend with v shortcut, write gated hi/lo
    float inv0 = 1.f / run_l0, inv1 = 1.f / run_l1;
    __syncthreads();
    #pragma unroll
    for (int nd = 0; nd < 4; nd++) {
        osm[nd * 8 + 2 * t][w * 16 + g]         = oacc[nd][0] * inv0;
        osm[nd * 8 + 2 * t + 1][w * 16 + g]     = oacc[nd][1] * inv0;
        osm[nd * 8 + 2 * t][w * 16 + g + 8]     = oacc[nd][2] * inv1;
        osm[nd * 8 + 2 * t + 1][w * 16 + g + 8] = oacc[nd][3] * inv1;
    }
    __syncthreads();

    const float* vfull = g_proj + ((long)b * MTOT + 512 + h * HD) * N_ + n0;
    int n = tid & 63;
    float sqv = g_sq[b * N_ + n0 + n];
    for (int d = tid >> 6; d < HD; d += 2) {
        float gated = sqv * osm[d][n] + (1.f - sqv) * vfull[(long)d * N_ + n];
        __nv_bfloat16 hi, lo; split_bf(gated, hi, lo);
        long gidx = ((long)b * C_ + h * HD + d) * N_ + n0 + n;
        g_ghi[gidx] = hi; g_glo[gidx] = lo;
    }
}

// ---------------- launch ----------------
extern "C" void kernel_launch(void* const* d_in, const int* in_sizes, int n_in,
                              void* d_out, int out_size) {
    const float* x   = (const float*)d_in[0];
    const float* gq  = (const float*)d_in[1];
    const float* gk  = (const float*)d_in[2];
    const float* Wsq = (const float*)d_in[3];
    const float* bsq = (const float*)d_in[4];
    const float* Wsk = (const float*)d_in[5];
    const float* bsk = (const float*)d_in[6];
    const float* Wq  = (const float*)d_in[7];
    const float* bq  = (const float*)d_in[8];
    const float* Wk  = (const float*)d_in[9];
    const float* bk  = (const float*)d_in[10];
    const float* Wv  = (const float*)d_in[11];
    const float* bv  = (const float*)d_in[12];
    const float* Wp  = (const float*)d_in[13];
    const float* bp  = (const float*)d_in[14];
    float* out = (float*)d_out;

    void *whi, *wlo, *ball, *wphi, *wplo, *xhi, *xlo, *proj, *ghi, *glo;
    cudaGetSymbolAddress(&whi,  g_whi);
    cudaGetSymbolAddress(&wlo,  g_wlo);
    cudaGetSymbolAddress(&ball, g_ball);
    cudaGetSymbolAddress(&wphi, g_wphi);
    cudaGetSymbolAddress(&wplo, g_wplo);
    cudaGetSymbolAddress(&xhi,  g_xhi);
    cudaGetSymbolAddress(&xlo,  g_xlo);
    cudaGetSymbolAddress(&proj, g_proj);
    cudaGetSymbolAddress(&ghi,  g_ghi);
    cudaGetSymbolAddress(&glo,  g_glo);

    // 1. weight assembly + bf16 splits
    assemble_split_kernel<<<MTOT + C_, 256>>>(Wq, bq, Wk, bk, Wv, bv, Wsq, bsq, Wsk, bsk, Wp);
    xsplit_kernel<<<(B_ * C_ * N_) / 256, 256>>>(x);

    // 2. fused projection GEMM (bf16x3): proj = Wall @ x
    {
        dim3 g(N_ / 128, (MTOT + 127) / 128, B_);
        gemm3x_kernel<<<g, 256>>>((const __nv_bfloat16*)whi, (const __nv_bfloat16*)wlo,
                                  (const float*)ball,
                                  (const __nv_bfloat16*)xhi, (const __nv_bfloat16*)xlo,
                                  (float*)proj, MTOT, (long)C_ * N_, (long)MTOT * N_);
    }

    // 3. gumbel-softmax gates
    gates_kernel<<<(B_ * N_ + 255) / 256, 256>>>(gq, gk);

    // 4. gate-scale + bf16 conversion (qT transpose, kB, vB)
    convert_kernel<<<B_ * NH, 256>>>();

    // 5. attention + fused blend -> gated bf16 hi/lo
    {
        dim3 g(N_ / 64, NH, B_);
        attn_kernel<<<g, 128>>>();
    }

    // 6. final projection GEMM (bf16x3): out = Wp @ gated
    {
        dim3 g(N_ / 128, C_ / 128, B_);
        gemm3x_kernel<<<g, 256>>>((const __nv_bfloat16*)wphi, (const __nv_bfloat16*)wplo,
                                  bp,
                                  (const __nv_bfloat16*)ghi, (const __nv_bfloat16*)glo,
                                  out, C_, (long)C_ * N_, (long)C_ * N_);
    }
}

// round 5
// speedup vs baseline: 3.4803x; 1.2938x over previous
#include <cuda_runtime.h>
#include <cuda_bf16.h>
#include <cstdint>

#define B_    8
#define C_    256
#define N_    1024
#define NH    8
#define HD    32
#define R_    4
#define MTOT  776
#define SCALE 0.17677669529663689f
#define LOG2E 1.4426950408889634f

// ---------------- scratch ----------------
__device__ float g_proj[B_ * MTOT * N_];
__device__ float g_sq[B_ * N_];
__device__ float g_ball[MTOT];
__device__ __nv_bfloat16 g_whi[MTOT * C_], g_wlo[MTOT * C_];
__device__ __nv_bfloat16 g_wphi[C_ * C_], g_wplo[C_ * C_];
__device__ __nv_bfloat16 g_xhi[B_ * C_ * N_], g_xlo[B_ * C_ * N_];
__device__ __nv_bfloat16 g_qB[B_ * C_ * N_];   // [b][c][n] gated*SCALE*LOG2E, c=h*32+d
__device__ __nv_bfloat16 g_kB[B_ * C_ * N_];   // gated
__device__ __nv_bfloat16 g_vB[B_ * C_ * N_];
__device__ __nv_bfloat16 g_ghi[B_ * C_ * N_], g_glo[B_ * C_ * N_];

// ---------------- ptx helpers ----------------
__device__ __forceinline__ void cp16(void* d, const void* s) {
    uint32_t ds = (uint32_t)__cvta_generic_to_shared(d);
    asm volatile("cp.async.cg.shared.global [%0], [%1], 16;" :: "r"(ds), "l"(s));
}
__device__ __forceinline__ void cp_commit() { asm volatile("cp.async.commit_group;"); }

__device__ __forceinline__ void ldsm_x4(uint32_t (&r)[4], const void* p) {
    uint32_t a = (uint32_t)__cvta_generic_to_shared(p);
    asm volatile("ldmatrix.sync.aligned.m8n8.x4.shared.b16 {%0,%1,%2,%3},[%4];"
                 : "=r"(r[0]), "=r"(r[1]), "=r"(r[2]), "=r"(r[3]) : "r"(a));
}
__device__ __forceinline__ void ldsm_x4t(uint32_t (&r)[4], const void* p) {
    uint32_t a = (uint32_t)__cvta_generic_to_shared(p);
    asm volatile("ldmatrix.sync.aligned.m8n8.x4.trans.shared.b16 {%0,%1,%2,%3},[%4];"
                 : "=r"(r[0]), "=r"(r[1]), "=r"(r[2]), "=r"(r[3]) : "r"(a));
}
__device__ __forceinline__ void ldsm_x2(uint32_t (&r)[2], const void* p) {
    uint32_t a = (uint32_t)__cvta_generic_to_shared(p);
    asm volatile("ldmatrix.sync.aligned.m8n8.x2.shared.b16 {%0,%1},[%2];"
                 : "=r"(r[0]), "=r"(r[1]) : "r"(a));
}
__device__ __forceinline__ void ldsm_x2t(uint32_t (&r)[2], const void* p) {
    uint32_t a = (uint32_t)__cvta_generic_to_shared(p);
    asm volatile("ldmatrix.sync.aligned.m8n8.x2.trans.shared.b16 {%0,%1},[%2];"
                 : "=r"(r[0]), "=r"(r[1]) : "r"(a));
}
__device__ __forceinline__ void mma16816(float (&d)[4], const uint32_t (&a)[4], const uint32_t (&b)[2]) {
    asm volatile(
        "mma.sync.aligned.m16n8k16.row.col.f32.bf16.bf16.f32 "
        "{%0,%1,%2,%3},{%4,%5,%6,%7},{%8,%9},{%0,%1,%2,%3};"
        : "+f"(d[0]), "+f"(d[1]), "+f"(d[2]), "+f"(d[3])
        : "r"(a[0]), "r"(a[1]), "r"(a[2]), "r"(a[3]), "r"(b[0]), "r"(b[1]));
}
__device__ __forceinline__ uint32_t packbf(float lo, float hi) {
    __nv_bfloat162 t = __floats2bfloat162_rn(lo, hi);
    return *reinterpret_cast<uint32_t*>(&t);
}
__device__ __forceinline__ float ex2(float x) {
    float y; asm("ex2.approx.ftz.f32 %0,%1;" : "=f"(y) : "f"(x)); return y;
}
__device__ __forceinline__ void split_bf(float x, __nv_bfloat16& hi, __nv_bfloat16& lo) {
    hi = __float2bfloat16_rn(x);
    lo = __float2bfloat16_rn(x - __bfloat162float(hi));
}

// ---------------- assemble + split weights ----------------
__global__ void assemble_split_kernel(
    const float* __restrict__ Wq, const float* __restrict__ bq,
    const float* __restrict__ Wk, const float* __restrict__ bk,
    const float* __restrict__ Wv, const float* __restrict__ bv,
    const float* __restrict__ Wsq, const float* __restrict__ bsq,
    const float* __restrict__ Wsk, const float* __restrict__ bsk,
    const float* __restrict__ Wp)
{
    int o = blockIdx.x;
    int k = threadIdx.x;
    if (o < MTOT) {
        const float* src; const float* bs; int r;
        if (o < 256)      { src = Wq  + o * 256;       bs = bq;  r = o; }
        else if (o < 512) { src = Wk  + (o-256) * 256; bs = bk;  r = o - 256; }
        else if (o < 768) { src = Wv  + (o-512) * 256; bs = bv;  r = o - 512; }
        else if (o < 772) { src = Wsq + (o-768) * 256; bs = bsq; r = o - 768; }
        else              { src = Wsk + (o-772) * 256; bs = bsk; r = o - 772; }
        __nv_bfloat16 hi, lo; split_bf(src[k], hi, lo);
        g_whi[o * 256 + k] = hi; g_wlo[o * 256 + k] = lo;
        if (k == 0) g_ball[o] = bs[r];
    } else {
        int r = o - MTOT;
        __nv_bfloat16 hi, lo; split_bf(Wp[r * 256 + k], hi, lo);
        g_wphi[r * 256 + k] = hi; g_wplo[r * 256 + k] = lo;
    }
}

// ---------------- split x into bf16 hi/lo ----------------
__global__ void xsplit_kernel(const float* __restrict__ x) {
    int i = blockIdx.x * 256 + threadIdx.x;
    __nv_bfloat16 hi, lo; split_bf(x[i], hi, lo);
    g_xhi[i] = hi; g_xlo[i] = lo;
}

// ---------------- bf16x3 GEMM ----------------
__global__ __launch_bounds__(256) void gemm3x_kernel(
    const __nv_bfloat16* __restrict__ Whi, const __nv_bfloat16* __restrict__ Wlo,
    const float* __restrict__ bias,
    const __nv_bfloat16* __restrict__ Xhi, const __nv_bfloat16* __restrict__ Xlo,
    float* __restrict__ Y, int M, long xStride, long yStride)
{
    int b  = blockIdx.z;
    int m0 = blockIdx.y * 128;
    int n0 = blockIdx.x * 128;
    const __nv_bfloat16* XhiB = Xhi + (long)b * xStride;
    const __nv_bfloat16* XloB = Xlo + (long)b * xStride;

    __shared__ __align__(16) __nv_bfloat16 sA[2][2][128 * 16];
    __shared__ __align__(16) __nv_bfloat16 sB[2][2][16 * 136];

    int tid  = threadIdx.x;
    int warp = tid >> 5, lane = tid & 31;
    int wm = warp >> 2, wn = warp & 3;
    int g = lane >> 2, t = lane & 3;

    float acc[4][4][4];
    #pragma unroll
    for (int mi = 0; mi < 4; mi++)
        #pragma unroll
        for (int ni = 0; ni < 4; ni++)
            #pragma unroll
            for (int r = 0; r < 4; r++) acc[mi][ni][r] = 0.f;

    auto loadStage = [&](int step, int s) {
        int k0 = step * 16;
        {
            int row = tid >> 1, half = tid & 1;
            int gm = m0 + row;
            __nv_bfloat16* dhi = &sA[s][0][row * 16 + half * 8];
            __nv_bfloat16* dlo = &sA[s][1][row * 16 + half * 8];
            if (gm < M) {
                cp16(dhi, Whi + gm * 256 + k0 + half * 8);
                cp16(dlo, Wlo + gm * 256 + k0 + half * 8);
            } else {
                *reinterpret_cast<uint4*>(dhi) = make_uint4(0,0,0,0);
                *reinterpret_cast<uint4*>(dlo) = make_uint4(0,0,0,0);
            }
        }
        {
            int row = tid >> 4, seg = tid & 15;
            cp16(&sB[s][0][row * 136 + seg * 8], XhiB + (long)(k0 + row) * N_ + n0 + seg * 8);
            cp16(&sB[s][1][row * 136 + seg * 8], XloB + (long)(k0 + row) * N_ + n0 + seg * 8);
        }
        cp_commit();
    };

    loadStage(0, 0);
    for (int step = 0; step < 16; step++) {
        int s = step & 1;
        if (step < 15) {
            loadStage(step + 1, s ^ 1);
            asm volatile("cp.async.wait_group 1;");
        } else {
            asm volatile("cp.async.wait_group 0;");
        }
        __syncthreads();

        uint32_t afr[2][4][4];
        #pragma unroll
        for (int v = 0; v < 2; v++)
            #pragma unroll
            for (int mi = 0; mi < 4; mi++) {
                const __nv_bfloat16* p = &sA[s][v][(wm * 64 + mi * 16 + (lane & 15)) * 16] + ((lane >> 4) & 1) * 8;
                ldsm_x4(afr[v][mi], p);
            }
        uint32_t bfr[2][4][2];
        #pragma unroll
        for (int v = 0; v < 2; v++)
            #pragma unroll
            for (int ni = 0; ni < 4; ni++) {
                const __nv_bfloat16* p = &sB[s][v][(lane & 15) * 136 + wn * 32 + ni * 8];
                ldsm_x2t(bfr[v][ni], p);
            }
        #pragma unroll
        for (int mi = 0; mi < 4; mi++)
            #pragma unroll
            for (int ni = 0; ni < 4; ni++) {
                mma16816(acc[mi][ni], afr[0][mi], bfr[0][ni]);
                mma16816(acc[mi][ni], afr[0][mi], bfr[1][ni]);
                mma16816(acc[mi][ni], afr[1][mi], bfr[0][ni]);
            }
        __syncthreads();
    }

    float* Yb = Y + (long)b * yStride;
    #pragma unroll
    for (int mi = 0; mi < 4; mi++) {
        int r0 = m0 + wm * 64 + mi * 16 + g;
        int r1 = r0 + 8;
        #pragma unroll
        for (int ni = 0; ni < 4; ni++) {
            int col = n0 + wn * 32 + ni * 8 + 2 * t;
            if (r0 < M) {
                float bv = bias[r0];
                Yb[(long)r0 * N_ + col]     = acc[mi][ni][0] + bv;
                Yb[(long)r0 * N_ + col + 1] = acc[mi][ni][1] + bv;
            }
            if (r1 < M) {
                float bv = bias[r1];
                Yb[(long)r1 * N_ + col]     = acc[mi][ni][2] + bv;
                Yb[(long)r1 * N_ + col + 1] = acc[mi][ni][3] + bv;
            }
        }
    }
}

// ---------------- fused gates + gate-scale + bf16 convert ----------------
// grid: 128 blocks = (b, 16 n-chunks of 64), 256 threads
__global__ __launch_bounds__(256) void convert_kernel(const float* __restrict__ gq,
                                                      const float* __restrict__ gk) {
    int b  = blockIdx.x >> 4;
    int n0 = (blockIdx.x & 15) * 64;
    int tid = threadIdx.x;
    const float* pr = g_proj + (long)b * MTOT * N_;
    const float QMUL = SCALE * LOG2E;

    __shared__ float ssq[64], ssk[64];
    if (tid < 64) {
        int n = n0 + tid;
        float lq[R_], lk[R_];
        #pragma unroll
        for (int r = 0; r < R_; r++) {
            lq[r] = pr[(768 + r) * N_ + n] + gq[(b * R_ + r) * N_ + n];
            lk[r] = pr[(772 + r) * N_ + n] + gk[(b * R_ + r) * N_ + n];
        }
        float mq = fmaxf(fmaxf(lq[0], lq[1]), fmaxf(lq[2], lq[3]));
        float s = 0.f;
        #pragma unroll
        for (int r = 0; r < R_; r++) s += __expf(lq[r] - mq);
        float sq = __expf(lq[0] - mq) / s;
        ssq[tid] = sq;
        g_sq[b * N_ + n] = sq;
        float mk = fmaxf(fmaxf(lk[0], lk[1]), fmaxf(lk[2], lk[3]));
        s = 0.f;
        #pragma unroll
        for (int r = 0; r < R_; r++) s += __expf(lk[r] - mk);
        ssk[tid] = __expf(lk[0] - mk) / s;
    }
    __syncthreads();

    for (int i = tid; i < 768 * 64; i += 256) {
        int row = i >> 6, n = i & 63;
        float val = pr[(long)row * N_ + n0 + n];
        if (row < 256) {
            g_qB[((long)b * C_ + row) * N_ + n0 + n] = __float2bfloat16_rn(val * ssq[n] * QMUL);
        } else if (row < 512) {
            g_kB[((long)b * C_ + row - 256) * N_ + n0 + n] = __float2bfloat16_rn(val * ssk[n]);
        } else {
            g_vB[((long)b * C_ + row - 512) * N_ + n0 + n] = __float2bfloat16_rn(val);
        }
    }
}

// ---------------- flash attention, no-max softmax, 128 queries/block ----------------
#define QSTR 136
#define KSTR 72
__global__ __launch_bounds__(256) void attn_kernel() {
    int b = blockIdx.z, h = blockIdx.y;
    int n0 = blockIdx.x * 128;
    const __nv_bfloat16* qBp = g_qB + ((long)b * C_ + h * HD) * N_;
    const __nv_bfloat16* kBp = g_kB + ((long)b * C_ + h * HD) * N_;
    const __nv_bfloat16* vBp = g_vB + ((long)b * C_ + h * HD) * N_;

    __shared__ __align__(16) __nv_bfloat16 qsm[32 * QSTR];       // [d][q]
    __shared__ __align__(16) __nv_bfloat16 ksm[2][32 * KSTR];    // [stage][d][key]
    __shared__ __align__(16) __nv_bfloat16 vsm[2][32 * KSTR];
    __shared__ float osm[32][130];

    int tid = threadIdx.x;
    int w = tid >> 5, lane = tid & 31;
    int g = lane >> 2, t = lane & 3;

    auto loadKV = [&](int m0, int s) {
        int row = tid >> 3, seg = tid & 7;
        cp16(&ksm[s][row * KSTR + seg * 8], kBp + (long)row * N_ + m0 + seg * 8);
        cp16(&vsm[s][row * KSTR + seg * 8], vBp + (long)row * N_ + m0 + seg * 8);
        cp_commit();
    };

    loadKV(0, 0);

    // Q tile: 32 rows x 256B = 512 chunks
    #pragma unroll
    for (int c = tid; c < 512; c += 256) {
        int row = c >> 4, seg = c & 15;
        reinterpret_cast<uint4*>(qsm + row * QSTR)[seg] =
            reinterpret_cast<const uint4*>(qBp + (long)row * N_ + n0)[seg];
    }
    __syncthreads();

    // A fragments via trans ldmatrix from [d][q]
    uint32_t aq[2][4];
    #pragma unroll
    for (int ku = 0; ku < 2; ku++) {
        int d = ku * 16 + ((lane >> 4) & 1) * 8 + (lane & 7);
        int col = w * 16 + ((lane >> 3) & 1) * 8;
        ldsm_x4t(aq[ku], qsm + d * QSTR + col);
    }

    float oacc[4][4];
    #pragma unroll
    for (int nd = 0; nd < 4; nd++)
        #pragma unroll
        for (int r = 0; r < 4; r++) oacc[nd][r] = 0.f;
    float l0 = 0.f, l1 = 0.f;

    for (int it = 0; it < 16; it++) {
        int s = it & 1;
        if (it < 15) {
            loadKV((it + 1) * 64, s ^ 1);
            asm volatile("cp.async.wait_group 1;");
        } else {
            asm volatile("cp.async.wait_group 0;");
        }
        __syncthreads();

        // S = Q^T K
        float sS[8][4];
        #pragma unroll
        for (int ni = 0; ni < 8; ni++) {
            #pragma unroll
            for (int r = 0; r < 4; r++) sS[ni][r] = 0.f;
            #pragma unroll
            for (int ku = 0; ku < 2; ku++) {
                uint32_t bk[2];
                ldsm_x2t(bk, &ksm[s][(ku * 16 + (lane & 15)) * KSTR + ni * 8]);
                mma16816(sS[ni], aq[ku], bk);
            }
        }

        // p = 2^s (no max subtraction; logits tiny), accumulate row sums
        #pragma unroll
        for (int ni = 0; ni < 8; ni++) {
            sS[ni][0] = ex2(sS[ni][0]); l0 += sS[ni][0];
            sS[ni][1] = ex2(sS[ni][1]); l0 += sS[ni][1];
            sS[ni][2] = ex2(sS[ni][2]); l1 += sS[ni][2];
            sS[ni][3] = ex2(sS[ni][3]); l1 += sS[ni][3];
        }

        // O += P V^T
        #pragma unroll
        for (int u = 0; u < 4; u++) {
            uint32_t ap[4];
            ap[0] = packbf(sS[2*u][0],   sS[2*u][1]);
            ap[1] = packbf(sS[2*u][2],   sS[2*u][3]);
            ap[2] = packbf(sS[2*u+1][0], sS[2*u+1][1]);
            ap[3] = packbf(sS[2*u+1][2], sS[2*u+1][3]);
            #pragma unroll
            for (int nd = 0; nd < 4; nd++) {
                uint32_t bv[2];
                ldsm_x2(bv, &vsm[s][(nd * 8 + (lane & 7)) * KSTR + u * 16 + ((lane >> 3) & 1) * 8]);
                mma16816(oacc[nd], ap, bv);
            }
        }
        __syncthreads();
    }

    // reduce l over the 4 t-lanes (same q row)
    #pragma unroll
    for (int off = 1; off < 4; off <<= 1) {
        l0 += __shfl_xor_sync(0xffffffffu, l0, off);
        l1 += __shfl_xor_sync(0xffffffffu, l1, off);
    }
    float inv0 = 1.f / l0, inv1 = 1.f / l1;

    #pragma unroll
    for (int nd = 0; nd < 4; nd++) {
        osm[nd * 8 + 2 * t][w * 16 + g]         = oacc[nd][0] * inv0;
        osm[nd * 8 + 2 * t + 1][w * 16 + g]     = oacc[nd][1] * inv0;
        osm[nd * 8 + 2 * t][w * 16 + g + 8]     = oacc[nd][2] * inv1;
        osm[nd * 8 + 2 * t + 1][w * 16 + g + 8] = oacc[nd][3] * inv1;
    }
    __syncthreads();

    // blend with v shortcut, emit gated hi/lo bf16
    const float* vfull = g_proj + ((long)b * MTOT + 512 + h * HD) * N_ + n0;
    int n = tid & 127;
    float sqv = g_sq[b * N_ + n0 + n];
    #pragma unroll
    for (int d = tid >> 7; d < HD; d += 2) {
        float gated = sqv * osm[d][n] + (1.f - sqv) * vfull[(long)d * N_ + n];
        __nv_bfloat16 hi, lo; split_bf(gated, hi, lo);
        long gidx = ((long)b * C_ + h * HD + d) * N_ + n0 + n;
        g_ghi[gidx] = hi; g_glo[gidx] = lo;
    }
}

// ---------------- launch ----------------
extern "C" void kernel_launch(void* const* d_in, const int* in_sizes, int n_in,
                              void* d_out, int out_size) {
    const float* x   = (const float*)d_in[0];
    const float* gq  = (const float*)d_in[1];
    const float* gk  = (const float*)d_in[2];
    const float* Wsq = (const float*)d_in[3];
    const float* bsq = (const float*)d_in[4];
    const float* Wsk = (const float*)d_in[5];
    const float* bsk = (const float*)d_in[6];
    const float* Wq  = (const float*)d_in[7];
    const float* bq  = (const float*)d_in[8];
    const float* Wk  = (const float*)d_in[9];
    const float* bk  = (const float*)d_in[10];
    const float* Wv  = (const float*)d_in[11];
    const float* bv  = (const float*)d_in[12];
    const float* Wp  = (const float*)d_in[13];
    const float* bp  = (const float*)d_in[14];
    float* out = (float*)d_out;

    void *whi, *wlo, *ball, *wphi, *wplo, *xhi, *xlo, *proj, *ghi, *glo;
    cudaGetSymbolAddress(&whi,  g_whi);
    cudaGetSymbolAddress(&wlo,  g_wlo);
    cudaGetSymbolAddress(&ball, g_ball);
    cudaGetSymbolAddress(&wphi, g_wphi);
    cudaGetSymbolAddress(&wplo, g_wplo);
    cudaGetSymbolAddress(&xhi,  g_xhi);
    cudaGetSymbolAddress(&xlo,  g_xlo);
    cudaGetSymbolAddress(&proj, g_proj);
    cudaGetSymbolAddress(&ghi,  g_ghi);
    cudaGetSymbolAddress(&glo,  g_glo);

    assemble_split_kernel<<<MTOT + C_, 256>>>(Wq, bq, Wk, bk, Wv, bv, Wsq, bsq, Wsk, bsk, Wp);
    xsplit_kernel<<<(B_ * C_ * N_) / 256, 256>>>(x);

    {   // proj = Wall @ x  (bf16x3)
        dim3 g(N_ / 128, (MTOT + 127) / 128, B_);
        gemm3x_kernel<<<g, 256>>>((const __nv_bfloat16*)whi, (const __nv_bfloat16*)wlo,
                                  (const float*)ball,
                                  (const __nv_bfloat16*)xhi, (const __nv_bfloat16*)xlo,
                                  (float*)proj, MTOT, (long)C_ * N_, (long)MTOT * N_);
    }

    convert_kernel<<<B_ * 16, 256>>>(gq, gk);

    {   // attention + blend
        dim3 g(N_ / 128, NH, B_);
        attn_kernel<<<g, 256>>>();
    }

    {   // out = Wp @ gated  (bf16x3)
        dim3 g(N_ / 128, C_ / 128, B_);
        gemm3x_kernel<<<g, 256>>>((const __nv_bfloat16*)wphi, (const __nv_bfloat16*)wplo,
                                  bp,
                                  (const __nv_bfloat16*)ghi, (const __nv_bfloat16*)glo,
                                  out, C_, (long)C_ * N_, (long)C_ * N_);
    }
}

// round 6
// speedup vs baseline: 5.0489x; 1.4507x over previous
#include <cuda_runtime.h>
#include <cuda_bf16.h>
#include <cstdint>

#define B_    8
#define C_    256
#define N_    1024
#define NH    8
#define HD    32
#define R_    4
#define MTOT  776
#define SCALE 0.17677669529663689f
#define LOG2E 1.4426950408889634f

// ---------------- scratch ----------------
__device__ float g_proj[B_ * MTOT * N_];
__device__ float g_sq[B_ * N_];
__device__ float g_sk[B_ * N_];
__device__ float g_ball[MTOT];
__device__ __nv_bfloat16 g_whi[MTOT * C_], g_wlo[MTOT * C_];
__device__ __nv_bfloat16 g_wphi[C_ * C_], g_wplo[C_ * C_];
__device__ __nv_bfloat16 g_xhi[B_ * C_ * N_], g_xlo[B_ * C_ * N_];
__device__ __nv_bfloat16 g_qB[B_ * C_ * N_];   // [b][c][n] gated*SCALE*LOG2E
__device__ __nv_bfloat16 g_kB[B_ * C_ * N_];   // gated
__device__ __nv_bfloat16 g_vB[B_ * C_ * N_];
__device__ __nv_bfloat16 g_ghi[B_ * C_ * N_], g_glo[B_ * C_ * N_];

// ---------------- ptx helpers ----------------
__device__ __forceinline__ void cp16(void* d, const void* s) {
    uint32_t ds = (uint32_t)__cvta_generic_to_shared(d);
    asm volatile("cp.async.cg.shared.global [%0], [%1], 16;" :: "r"(ds), "l"(s));
}
__device__ __forceinline__ void cp_commit() { asm volatile("cp.async.commit_group;"); }

__device__ __forceinline__ void ldsm_x4(uint32_t (&r)[4], const void* p) {
    uint32_t a = (uint32_t)__cvta_generic_to_shared(p);
    asm volatile("ldmatrix.sync.aligned.m8n8.x4.shared.b16 {%0,%1,%2,%3},[%4];"
                 : "=r"(r[0]), "=r"(r[1]), "=r"(r[2]), "=r"(r[3]) : "r"(a));
}
__device__ __forceinline__ void ldsm_x4t(uint32_t (&r)[4], const void* p) {
    uint32_t a = (uint32_t)__cvta_generic_to_shared(p);
    asm volatile("ldmatrix.sync.aligned.m8n8.x4.trans.shared.b16 {%0,%1,%2,%3},[%4];"
                 : "=r"(r[0]), "=r"(r[1]), "=r"(r[2]), "=r"(r[3]) : "r"(a));
}
__device__ __forceinline__ void ldsm_x2(uint32_t (&r)[2], const void* p) {
    uint32_t a = (uint32_t)__cvta_generic_to_shared(p);
    asm volatile("ldmatrix.sync.aligned.m8n8.x2.shared.b16 {%0,%1},[%2];"
                 : "=r"(r[0]), "=r"(r[1]) : "r"(a));
}
__device__ __forceinline__ void ldsm_x2t(uint32_t (&r)[2], const void* p) {
    uint32_t a = (uint32_t)__cvta_generic_to_shared(p);
    asm volatile("ldmatrix.sync.aligned.m8n8.x2.trans.shared.b16 {%0,%1},[%2];"
                 : "=r"(r[0]), "=r"(r[1]) : "r"(a));
}
__device__ __forceinline__ void mma16816(float (&d)[4], const uint32_t (&a)[4], const uint32_t (&b)[2]) {
    asm volatile(
        "mma.sync.aligned.m16n8k16.row.col.f32.bf16.bf16.f32 "
        "{%0,%1,%2,%3},{%4,%5,%6,%7},{%8,%9},{%0,%1,%2,%3};"
        : "+f"(d[0]), "+f"(d[1]), "+f"(d[2]), "+f"(d[3])
        : "r"(a[0]), "r"(a[1]), "r"(a[2]), "r"(a[3]), "r"(b[0]), "r"(b[1]));
}
__device__ __forceinline__ uint32_t packbf(float lo, float hi) {
    __nv_bfloat162 t = __floats2bfloat162_rn(lo, hi);
    return *reinterpret_cast<uint32_t*>(&t);
}
__device__ __forceinline__ float ex2(float x) {
    float y; asm("ex2.approx.ftz.f32 %0,%1;" : "=f"(y) : "f"(x)); return y;
}
__device__ __forceinline__ void split_bf(float x, __nv_bfloat16& hi, __nv_bfloat16& lo) {
    hi = __float2bfloat16_rn(x);
    lo = __float2bfloat16_rn(x - __bfloat162float(hi));
}

// ---------------- assemble + split weights ----------------
__global__ void assemble_split_kernel(
    const float* __restrict__ Wq, const float* __restrict__ bq,
    const float* __restrict__ Wk, const float* __restrict__ bk,
    const float* __restrict__ Wv, const float* __restrict__ bv,
    const float* __restrict__ Wsq, const float* __restrict__ bsq,
    const float* __restrict__ Wsk, const float* __restrict__ bsk,
    const float* __restrict__ Wp)
{
    int o = blockIdx.x;
    int k = threadIdx.x;
    if (o < MTOT) {
        const float* src; const float* bs; int r;
        if (o < 256)      { src = Wq  + o * 256;       bs = bq;  r = o; }
        else if (o < 512) { src = Wk  + (o-256) * 256; bs = bk;  r = o - 256; }
        else if (o < 768) { src = Wv  + (o-512) * 256; bs = bv;  r = o - 512; }
        else if (o < 772) { src = Wsq + (o-768) * 256; bs = bsq; r = o - 768; }
        else              { src = Wsk + (o-772) * 256; bs = bsk; r = o - 772; }
        __nv_bfloat16 hi, lo; split_bf(src[k], hi, lo);
        g_whi[o * 256 + k] = hi; g_wlo[o * 256 + k] = lo;
        if (k == 0) g_ball[o] = bs[r];
    } else {
        int r = o - MTOT;
        __nv_bfloat16 hi, lo; split_bf(Wp[r * 256 + k], hi, lo);
        g_wphi[r * 256 + k] = hi; g_wplo[r * 256 + k] = lo;
    }
}

// ---------------- split x into bf16 hi/lo ----------------
__global__ void xsplit_kernel(const float* __restrict__ x) {
    int i = blockIdx.x * 256 + threadIdx.x;
    __nv_bfloat16 hi, lo; split_bf(x[i], hi, lo);
    g_xhi[i] = hi; g_xlo[i] = lo;
}

// ---------------- bf16x3 GEMM ----------------
__global__ __launch_bounds__(256) void gemm3x_kernel(
    const __nv_bfloat16* __restrict__ Whi, const __nv_bfloat16* __restrict__ Wlo,
    const float* __restrict__ bias,
    const __nv_bfloat16* __restrict__ Xhi, const __nv_bfloat16* __restrict__ Xlo,
    float* __restrict__ Y, int M, long xStride, long yStride)
{
    int b  = blockIdx.z;
    int m0 = blockIdx.y * 128;
    int n0 = blockIdx.x * 128;
    const __nv_bfloat16* XhiB = Xhi + (long)b * xStride;
    const __nv_bfloat16* XloB = Xlo + (long)b * xStride;

    __shared__ __align__(16) __nv_bfloat16 sA[2][2][128 * 16];
    __shared__ __align__(16) __nv_bfloat16 sB[2][2][16 * 136];

    int tid  = threadIdx.x;
    int warp = tid >> 5, lane = tid & 31;
    int wm = warp >> 2, wn = warp & 3;
    int g = lane >> 2, t = lane & 3;

    float acc[4][4][4];
    #pragma unroll
    for (int mi = 0; mi < 4; mi++)
        #pragma unroll
        for (int ni = 0; ni < 4; ni++)
            #pragma unroll
            for (int r = 0; r < 4; r++) acc[mi][ni][r] = 0.f;

    auto loadStage = [&](int step, int s) {
        int k0 = step * 16;
        {
            int row = tid >> 1, half = tid & 1;
            int gm = m0 + row;
            __nv_bfloat16* dhi = &sA[s][0][row * 16 + half * 8];
            __nv_bfloat16* dlo = &sA[s][1][row * 16 + half * 8];
            if (gm < M) {
                cp16(dhi, Whi + gm * 256 + k0 + half * 8);
                cp16(dlo, Wlo + gm * 256 + k0 + half * 8);
            } else {
                *reinterpret_cast<uint4*>(dhi) = make_uint4(0,0,0,0);
                *reinterpret_cast<uint4*>(dlo) = make_uint4(0,0,0,0);
            }
        }
        {
            int row = tid >> 4, seg = tid & 15;
            cp16(&sB[s][0][row * 136 + seg * 8], XhiB + (long)(k0 + row) * N_ + n0 + seg * 8);
            cp16(&sB[s][1][row * 136 + seg * 8], XloB + (long)(k0 + row) * N_ + n0 + seg * 8);
        }
        cp_commit();
    };

    loadStage(0, 0);
    for (int step = 0; step < 16; step++) {
        int s = step & 1;
        if (step < 15) {
            loadStage(step + 1, s ^ 1);
            asm volatile("cp.async.wait_group 1;");
        } else {
            asm volatile("cp.async.wait_group 0;");
        }
        __syncthreads();

        uint32_t afr[2][4][4];
        #pragma unroll
        for (int v = 0; v < 2; v++)
            #pragma unroll
            for (int mi = 0; mi < 4; mi++) {
                const __nv_bfloat16* p = &sA[s][v][(wm * 64 + mi * 16 + (lane & 15)) * 16] + ((lane >> 4) & 1) * 8;
                ldsm_x4(afr[v][mi], p);
            }
        uint32_t bfr[2][4][2];
        #pragma unroll
        for (int v = 0; v < 2; v++)
            #pragma unroll
            for (int ni = 0; ni < 4; ni++) {
                const __nv_bfloat16* p = &sB[s][v][(lane & 15) * 136 + wn * 32 + ni * 8];
                ldsm_x2t(bfr[v][ni], p);
            }
        #pragma unroll
        for (int mi = 0; mi < 4; mi++)
            #pragma unroll
            for (int ni = 0; ni < 4; ni++) {
                mma16816(acc[mi][ni], afr[0][mi], bfr[0][ni]);
                mma16816(acc[mi][ni], afr[0][mi], bfr[1][ni]);
                mma16816(acc[mi][ni], afr[1][mi], bfr[0][ni]);
            }
        __syncthreads();
    }

    float* Yb = Y + (long)b * yStride;
    #pragma unroll
    for (int mi = 0; mi < 4; mi++) {
        int r0 = m0 + wm * 64 + mi * 16 + g;
        int r1 = r0 + 8;
        #pragma unroll
        for (int ni = 0; ni < 4; ni++) {
            int col = n0 + wn * 32 + ni * 8 + 2 * t;
            if (r0 < M) {
                float bv = bias[r0];
                Yb[(long)r0 * N_ + col]     = acc[mi][ni][0] + bv;
                Yb[(long)r0 * N_ + col + 1] = acc[mi][ni][1] + bv;
            }
            if (r1 < M) {
                float bv = bias[r1];
                Yb[(long)r1 * N_ + col]     = acc[mi][ni][2] + bv;
                Yb[(long)r1 * N_ + col + 1] = acc[mi][ni][3] + bv;
            }
        }
    }
}

// ---------------- gates: 4-way softmax per pixel ----------------
__global__ void gates_kernel(const float* __restrict__ gq, const float* __restrict__ gk) {
    int idx = blockIdx.x * blockDim.x + threadIdx.x;
    if (idx >= B_ * N_) return;
    int b = idx >> 10, n = idx & 1023;
    const float* pr = g_proj + (long)b * MTOT * N_;
    float lq[R_], lk[R_];
    #pragma unroll
    for (int r = 0; r < R_; r++) {
        lq[r] = pr[(768 + r) * N_ + n] + gq[(b * R_ + r) * N_ + n];
        lk[r] = pr[(772 + r) * N_ + n] + gk[(b * R_ + r) * N_ + n];
    }
    float mq = fmaxf(fmaxf(lq[0], lq[1]), fmaxf(lq[2], lq[3]));
    float s = 0.f;
    #pragma unroll
    for (int r = 0; r < R_; r++) s += __expf(lq[r] - mq);
    g_sq[idx] = __expf(lq[0] - mq) / s;
    float mk = fmaxf(fmaxf(lk[0], lk[1]), fmaxf(lk[2], lk[3]));
    s = 0.f;
    #pragma unroll
    for (int r = 0; r < R_; r++) s += __expf(lk[r] - mk);
    g_sk[idx] = __expf(lk[0] - mk) / s;
}

// ---------------- wide elementwise convert: one row per block, float4 per thread ----------------
__global__ __launch_bounds__(256) void convert_kernel() {
    int row = blockIdx.x;        // 0..767
    int b   = blockIdx.y;
    int n   = threadIdx.x * 4;
    const float QMUL = SCALE * LOG2E;

    float4 v = *reinterpret_cast<const float4*>(g_proj + ((long)b * MTOT + row) * N_ + n);
    uint2 outp;
    if (row < 256) {
        float4 s = *reinterpret_cast<const float4*>(g_sq + b * N_ + n);
        outp.x = packbf(v.x * s.x * QMUL, v.y * s.y * QMUL);
        outp.y = packbf(v.z * s.z * QMUL, v.w * s.w * QMUL);
        *reinterpret_cast<uint2*>(g_qB + ((long)b * C_ + row) * N_ + n) = outp;
    } else if (row < 512) {
        float4 s = *reinterpret_cast<const float4*>(g_sk + b * N_ + n);
        outp.x = packbf(v.x * s.x, v.y * s.y);
        outp.y = packbf(v.z * s.z, v.w * s.w);
        *reinterpret_cast<uint2*>(g_kB + ((long)b * C_ + row - 256) * N_ + n) = outp;
    } else {
        outp.x = packbf(v.x, v.y);
        outp.y = packbf(v.z, v.w);
        *reinterpret_cast<uint2*>(g_vB + ((long)b * C_ + row - 512) * N_ + n) = outp;
    }
}

// ---------------- flash attention, no-max softmax, 128 queries/block ----------------
#define QSTR 136
#define KSTR 72
__global__ __launch_bounds__(256) void attn_kernel() {
    int b = blockIdx.z, h = blockIdx.y;
    int n0 = blockIdx.x * 128;
    const __nv_bfloat16* qBp = g_qB + ((long)b * C_ + h * HD) * N_;
    const __nv_bfloat16* kBp = g_kB + ((long)b * C_ + h * HD) * N_;
    const __nv_bfloat16* vBp = g_vB + ((long)b * C_ + h * HD) * N_;

    __shared__ __align__(16) __nv_bfloat16 qsm[32 * QSTR];       // [d][q]
    __shared__ __align__(16) __nv_bfloat16 ksm[2][32 * KSTR];    // [stage][d][key]
    __shared__ __align__(16) __nv_bfloat16 vsm[2][32 * KSTR];
    __shared__ float osm[32][130];

    int tid = threadIdx.x;
    int w = tid >> 5, lane = tid & 31;
    int g = lane >> 2, t = lane & 3;

    auto loadKV = [&](int m0, int s) {
        int row = tid >> 3, seg = tid & 7;
        cp16(&ksm[s][row * KSTR + seg * 8], kBp + (long)row * N_ + m0 + seg * 8);
        cp16(&vsm[s][row * KSTR + seg * 8], vBp + (long)row * N_ + m0 + seg * 8);
        cp_commit();
    };

    loadKV(0, 0);

    #pragma unroll
    for (int c = tid; c < 512; c += 256) {
        int row = c >> 4, seg = c & 15;
        reinterpret_cast<uint4*>(qsm + row * QSTR)[seg] =
            reinterpret_cast<const uint4*>(qBp + (long)row * N_ + n0)[seg];
    }
    __syncthreads();

    uint32_t aq[2][4];
    #pragma unroll
    for (int ku = 0; ku < 2; ku++) {
        int d = ku * 16 + ((lane >> 4) & 1) * 8 + (lane & 7);
        int col = w * 16 + ((lane >> 3) & 1) * 8;
        ldsm_x4t(aq[ku], qsm + d * QSTR + col);
    }

    float oacc[4][4];
    #pragma unroll
    for (int nd = 0; nd < 4; nd++)
        #pragma unroll
        for (int r = 0; r < 4; r++) oacc[nd][r] = 0.f;
    float l0 = 0.f, l1 = 0.f;

    for (int it = 0; it < 16; it++) {
        int s = it & 1;
        if (it < 15) {
            loadKV((it + 1) * 64, s ^ 1);
            asm volatile("cp.async.wait_group 1;");
        } else {
            asm volatile("cp.async.wait_group 0;");
        }
        __syncthreads();

        float sS[8][4];
        #pragma unroll
        for (int ni = 0; ni < 8; ni++) {
            #pragma unroll
            for (int r = 0; r < 4; r++) sS[ni][r] = 0.f;
            #pragma unroll
            for (int ku = 0; ku < 2; ku++) {
                uint32_t bk[2];
                ldsm_x2t(bk, &ksm[s][(ku * 16 + (lane & 15)) * KSTR + ni * 8]);
                mma16816(sS[ni], aq[ku], bk);
            }
        }

        #pragma unroll
        for (int ni = 0; ni < 8; ni++) {
            sS[ni][0] = ex2(sS[ni][0]); l0 += sS[ni][0];
            sS[ni][1] = ex2(sS[ni][1]); l0 += sS[ni][1];
            sS[ni][2] = ex2(sS[ni][2]); l1 += sS[ni][2];
            sS[ni][3] = ex2(sS[ni][3]); l1 += sS[ni][3];
        }

        #pragma unroll
        for (int u = 0; u < 4; u++) {
            uint32_t ap[4];
            ap[0] = packbf(sS[2*u][0],   sS[2*u][1]);
            ap[1] = packbf(sS[2*u][2],   sS[2*u][3]);
            ap[2] = packbf(sS[2*u+1][0], sS[2*u+1][1]);
            ap[3] = packbf(sS[2*u+1][2], sS[2*u+1][3]);
            #pragma unroll
            for (int nd = 0; nd < 4; nd++) {
                uint32_t bv[2];
                ldsm_x2(bv, &vsm[s][(nd * 8 + (lane & 7)) * KSTR + u * 16 + ((lane >> 3) & 1) * 8]);
                mma16816(oacc[nd], ap, bv);
            }
        }
        __syncthreads();
    }

    #pragma unroll
    for (int off = 1; off < 4; off <<= 1) {
        l0 += __shfl_xor_sync(0xffffffffu, l0, off);
        l1 += __shfl_xor_sync(0xffffffffu, l1, off);
    }
    float inv0 = 1.f / l0, inv1 = 1.f / l1;

    #pragma unroll
    for (int nd = 0; nd < 4; nd++) {
        osm[nd * 8 + 2 * t][w * 16 + g]         = oacc[nd][0] * inv0;
        osm[nd * 8 + 2 * t + 1][w * 16 + g]     = oacc[nd][1] * inv0;
        osm[nd * 8 + 2 * t][w * 16 + g + 8]     = oacc[nd][2] * inv1;
        osm[nd * 8 + 2 * t + 1][w * 16 + g + 8] = oacc[nd][3] * inv1;
    }
    __syncthreads();

    const float* vfull = g_proj + ((long)b * MTOT + 512 + h * HD) * N_ + n0;
    int n = tid & 127;
    float sqv = g_sq[b * N_ + n0 + n];
    #pragma unroll
    for (int d = tid >> 7; d < HD; d += 2) {
        float gated = sqv * osm[d][n] + (1.f - sqv) * vfull[(long)d * N_ + n];
        __nv_bfloat16 hi, lo; split_bf(gated, hi, lo);
        long gidx = ((long)b * C_ + h * HD + d) * N_ + n0 + n;
        g_ghi[gidx] = hi; g_glo[gidx] = lo;
    }
}

// ---------------- launch ----------------
extern "C" void kernel_launch(void* const* d_in, const int* in_sizes, int n_in,
                              void* d_out, int out_size) {
    const float* x   = (const float*)d_in[0];
    const float* gq  = (const float*)d_in[1];
    const float* gk  = (const float*)d_in[2];
    const float* Wsq = (const float*)d_in[3];
    const float* bsq = (const float*)d_in[4];
    const float* Wsk = (const float*)d_in[5];
    const float* bsk = (const float*)d_in[6];
    const float* Wq  = (const float*)d_in[7];
    const float* bq  = (const float*)d_in[8];
    const float* Wk  = (const float*)d_in[9];
    const float* bk  = (const float*)d_in[10];
    const float* Wv  = (const float*)d_in[11];
    const float* bv  = (const float*)d_in[12];
    const float* Wp  = (const float*)d_in[13];
    const float* bp  = (const float*)d_in[14];
    float* out = (float*)d_out;

    void *whi, *wlo, *ball, *wphi, *wplo, *xhi, *xlo, *proj, *ghi, *glo;
    cudaGetSymbolAddress(&whi,  g_whi);
    cudaGetSymbolAddress(&wlo,  g_wlo);
    cudaGetSymbolAddress(&ball, g_ball);
    cudaGetSymbolAddress(&wphi, g_wphi);
    cudaGetSymbolAddress(&wplo, g_wplo);
    cudaGetSymbolAddress(&xhi,  g_xhi);
    cudaGetSymbolAddress(&xlo,  g_xlo);
    cudaGetSymbolAddress(&proj, g_proj);
    cudaGetSymbolAddress(&ghi,  g_ghi);
    cudaGetSymbolAddress(&glo,  g_glo);

    assemble_split_kernel<<<MTOT + C_, 256>>>(Wq, bq, Wk, bk, Wv, bv, Wsq, bsq, Wsk, bsk, Wp);
    xsplit_kernel<<<(B_ * C_ * N_) / 256, 256>>>(x);

    {   // proj = Wall @ x  (bf16x3)
        dim3 g(N_ / 128, (MTOT + 127) / 128, B_);
        gemm3x_kernel<<<g, 256>>>((const __nv_bfloat16*)whi, (const __nv_bfloat16*)wlo,
                                  (const float*)ball,
                                  (const __nv_bfloat16*)xhi, (const __nv_bfloat16*)xlo,
                                  (float*)proj, MTOT, (long)C_ * N_, (long)MTOT * N_);
    }

    gates_kernel<<<(B_ * N_ + 255) / 256, 256>>>(gq, gk);

    {   // wide elementwise convert
        dim3 g(768, B_);
        convert_kernel<<<g, 256>>>();
    }

    {   // attention + blend
        dim3 g(N_ / 128, NH, B_);
        attn_kernel<<<g, 256>>>();
    }

    {   // out = Wp @ gated  (bf16x3)
        dim3 g(N_ / 128, C_ / 128, B_);
        gemm3x_kernel<<<g, 256>>>((const __nv_bfloat16*)wphi, (const __nv_bfloat16*)wplo,
                                  bp,
                                  (const __nv_bfloat16*)ghi, (const __nv_bfloat16*)glo,
                                  out, C_, (long)C_ * N_, (long)C_ * N_);
    }
}